// round 10
// baseline (speedup 1.0000x reference)
#include <cuda_runtime.h>
#include <cuda_bf16.h>
#include <cuda_fp16.h>
#include <cstdint>

#define NN 50000
#define EE 800000
#define DD 128

#define ASTR 136                     // padded row stride in bf16 (272B; conflict-free ldmatrix)
#define ATB (64 * ASTR * 2)          // 17408 B : 64-row A image (hi or lo)
#define BTB (128 * ASTR * 2)         // 34816 B : 128-row B image (hi or lo)
#define SMEMSZ (2 * ATB + 2 * BTB)   // 104448 B : sAh | sAl | sBh | sBl  (2 CTAs/SM)
#define WBYTES (2 * BTB)

// ---------------- scratch (static device globals; no allocation) ----------------
__device__ float g_S[NN * DD];
__device__ float g_H[NN * DD];
__device__ float g_T[NN * DD];
__device__ __half g_X16[NN * DD];   // fp16 copy of x   (gather-0 neighbor source)
__device__ __half g_T16[NN * DD];   // fp16 copy of T   (gather-1 neighbor source)
__device__ __align__(16) float g_stats[3 * 256];
__device__ unsigned char g_WB[4][WBYTES];
__device__ int g_deg[NN];
__device__ int g_pos[EE];
__device__ int g_off[NN + 1];
__device__ int g_adj[EE];

// ---------------- helpers ----------------
__device__ __forceinline__ uint32_t smem_u32(const void* p) {
    uint32_t a;
    asm("{ .reg .u64 t; cvta.to.shared.u64 t, %1; cvt.u32.u64 %0, t; }" : "=r"(a) : "l"(p));
    return a;
}

__device__ __forceinline__ void cp16(uint32_t s, const void* g) {
    asm volatile("cp.async.ca.shared.global [%0], [%1], 16;" :: "r"(s), "l"(g));
}

__device__ __forceinline__ void ldmx4(uint32_t* r, uint32_t addr) {
    asm volatile("ldmatrix.sync.aligned.m8n8.x4.shared.b16 {%0,%1,%2,%3}, [%4];"
                 : "=r"(r[0]), "=r"(r[1]), "=r"(r[2]), "=r"(r[3]) : "r"(addr));
}

__device__ __forceinline__ void mma16816(float* d, const uint32_t* a, uint32_t b0, uint32_t b1) {
    asm volatile(
        "mma.sync.aligned.m16n8k16.row.col.f32.bf16.bf16.f32 "
        "{%0,%1,%2,%3}, {%4,%5,%6,%7}, {%8,%9}, {%0,%1,%2,%3};"
        : "+f"(d[0]), "+f"(d[1]), "+f"(d[2]), "+f"(d[3])
        : "r"(a[0]), "r"(a[1]), "r"(a[2]), "r"(a[3]), "r"(b0), "r"(b1));
}

// load 4 fp16 (8B) -> float4
__device__ __forceinline__ float4 ldg_h4(const __half* p) {
    uint2 r = __ldg(reinterpret_cast<const uint2*>(p));
    __half2 h0 = *reinterpret_cast<__half2*>(&r.x);
    __half2 h1 = *reinterpret_cast<__half2*>(&r.y);
    float2 f0 = __half22float2(h0), f1 = __half22float2(h1);
    return make_float4(f0.x, f0.y, f1.x, f1.y);
}

// BN coef for 4 channels [k0..k0+3] from raw stats
__device__ __forceinline__ void bn4(const float* __restrict__ st, const float* __restrict__ g,
                                    const float* __restrict__ be, int k0, float4& a, float4& b) {
    float4 s = __ldg(reinterpret_cast<const float4*>(&st[k0]));
    float4 q = __ldg(reinterpret_cast<const float4*>(&st[128 + k0]));
    float4 gg = __ldg(reinterpret_cast<const float4*>(&g[k0]));
    float4 bb = __ldg(reinterpret_cast<const float4*>(&be[k0]));
    const float inv = 1.f / NN;
    float m;
    m = s.x * inv; a.x = gg.x * rsqrtf(q.x * inv - m * m + 1e-5f); b.x = bb.x - m * a.x;
    m = s.y * inv; a.y = gg.y * rsqrtf(q.y * inv - m * m + 1e-5f); b.y = bb.y - m * a.y;
    m = s.z * inv; a.z = gg.z * rsqrtf(q.z * inv - m * m + 1e-5f); b.z = bb.z - m * a.z;
    m = s.w * inv; a.w = gg.w * rsqrtf(q.w * inv - m * m + 1e-5f); b.w = bb.w - m * a.w;
}

// ---------------- prep: zero stats/deg + W split + x -> fp16 copy ----------------
__global__ void prep_kernel(const float* __restrict__ x,
                            const float* __restrict__ w0, const float* __restrict__ w1,
                            const float* __restrict__ w2, const float* __restrict__ w3) {
    int b = blockIdx.x;  // 0..255
    int gt = b * 256 + threadIdx.x;
    for (int z = gt; z < NN; z += 256 * 256) g_deg[z] = 0;
    if (b == 0) {
        for (int j = threadIdx.x; j < 3 * 256; j += 256) g_stats[j] = 0.f;
    }
    // x -> fp16 copy (6.4M elements as float4)
    for (int i = gt; i < NN * DD / 4; i += 256 * 256) {
        float4 v = __ldg(reinterpret_cast<const float4*>(x) + i);
        __half2 a = __floats2half2_rn(v.x, v.y);
        __half2 c2 = __floats2half2_rn(v.z, v.w);
        uint2 o;
        o.x = *reinterpret_cast<uint32_t*>(&a);
        o.y = *reinterpret_cast<uint32_t*>(&c2);
        reinterpret_cast<uint2*>(g_X16)[i] = o;
    }
    // W split: 64 blocks per weight matrix
    int widx = b >> 6;
    const float* W = (widx == 0) ? w0 : (widx == 1) ? w1 : (widx == 2) ? w2 : w3;
    unsigned char* WB = g_WB[widx];
    int idx = (b & 63) * 256 + threadIdx.x;  // 0..16383
    int k = idx >> 7, c = idx & 127;
    float w = W[idx];
    __nv_bfloat16 h = __float2bfloat16(w);
    __nv_bfloat16 l = __float2bfloat16(w - __bfloat162float(h));
    uint32_t off = ((uint32_t)c * ASTR + (uint32_t)k) * 2;
    *reinterpret_cast<__nv_bfloat16*>(WB + off) = h;
    *reinterpret_cast<__nv_bfloat16*>(WB + BTB + off) = l;
}

// ---------------- CSR build ----------------
__global__ void hist_kernel(const int* __restrict__ row) {
    int e = blockIdx.x * 256 + threadIdx.x;
    if (e < EE) g_pos[e] = atomicAdd(&g_deg[__ldg(&row[e])], 1);
}

__global__ void scan_kernel() {  // single block, 1024 threads
    __shared__ int ps[1024];
    const int t = threadIdx.x;
    const int CH = (NN + 1023) / 1024;  // 49
    const int base = t * CH;
    int s = 0;
#pragma unroll 7
    for (int i = 0; i < CH; i++) {
        int n = base + i;
        if (n < NN) s += g_deg[n];
    }
    ps[t] = s;
    __syncthreads();
    for (int d = 1; d < 1024; d <<= 1) {
        int v = (t >= d) ? ps[t - d] : 0;
        __syncthreads();
        ps[t] += v;
        __syncthreads();
    }
    int run = (t == 0) ? 0 : ps[t - 1];
#pragma unroll 7
    for (int i = 0; i < CH; i++) {
        int n = base + i;
        if (n < NN) {
            g_off[n] = run;
            run += g_deg[n];
        }
    }
    if (t == 1023) g_off[NN] = run;
}

__global__ void fill_kernel(const int* __restrict__ row, const int* __restrict__ col) {
    int e = blockIdx.x * 256 + threadIdx.x;
    if (e >= EE) return;
    int r = __ldg(&row[e]);
    g_adj[__ldg(&g_off[r]) + g_pos[e]] = __ldg(&col[e]);
}

// ---------------- gather: dst[i] = pre(featSelf[i]) + sum_j pre(feat16[adj[j]]) ----------------
template <bool PRE>
__global__ void gather_kernel(const float* __restrict__ featSelf, const __half* __restrict__ feat16,
                              const float* __restrict__ stats,
                              const float* __restrict__ bng, const float* __restrict__ bnb,
                              float* __restrict__ dst) {
    int node = (blockIdx.x * blockDim.x + threadIdx.x) >> 5;
    if (node >= NN) return;
    const int lane = threadIdx.x & 31;
    const int k0 = lane * 4;

    float4 ca, cb;
    if (PRE) bn4(stats, bng, bnb, k0, ca, cb);
#define PREV(v)                                      \
    if (PRE) {                                       \
        (v).x = fmaxf(ca.x * (v).x + cb.x, 0.f);     \
        (v).y = fmaxf(ca.y * (v).y + cb.y, 0.f);     \
        (v).z = fmaxf(ca.z * (v).z + cb.z, 0.f);     \
        (v).w = fmaxf(ca.w * (v).w + cb.w, 0.f);     \
    }

    // self from fp32 source (full precision)
    float4 acc = __ldg(reinterpret_cast<const float4*>(&featSelf[(size_t)node * DD + k0]));
    PREV(acc);

    const int s = __ldg(&g_off[node]);
    const int e = __ldg(&g_off[node + 1]);
    int j = s;
    for (; j + 4 <= e; j += 4) {
        int c0 = __ldg(&g_adj[j + 0]);
        int c1 = __ldg(&g_adj[j + 1]);
        int c2 = __ldg(&g_adj[j + 2]);
        int c3 = __ldg(&g_adj[j + 3]);
        float4 v0 = ldg_h4(&feat16[(size_t)c0 * DD + k0]);
        float4 v1 = ldg_h4(&feat16[(size_t)c1 * DD + k0]);
        float4 v2 = ldg_h4(&feat16[(size_t)c2 * DD + k0]);
        float4 v3 = ldg_h4(&feat16[(size_t)c3 * DD + k0]);
        PREV(v0); PREV(v1); PREV(v2); PREV(v3);
        acc.x += (v0.x + v1.x) + (v2.x + v3.x);
        acc.y += (v0.y + v1.y) + (v2.y + v3.y);
        acc.z += (v0.z + v1.z) + (v2.z + v3.z);
        acc.w += (v0.w + v1.w) + (v2.w + v3.w);
    }
    for (; j < e; j++) {
        int c = __ldg(&g_adj[j]);
        float4 v = ldg_h4(&feat16[(size_t)c * DD + k0]);
        PREV(v);
        acc.x += v.x; acc.y += v.y; acc.z += v.z; acc.w += v.w;
    }
    *reinterpret_cast<float4*>(&dst[(size_t)node * DD + k0]) = acc;
#undef PREV
}

// ---------------- column sum & sumsq over NN rows ----------------
__global__ void stats_kernel(const float4* __restrict__ buf, float* __restrict__ st) {
    int c4 = threadIdx.x & 31, rt = threadIdx.x >> 5;
    float ls[4] = {0.f, 0.f, 0.f, 0.f}, lq[4] = {0.f, 0.f, 0.f, 0.f};
    for (int r = blockIdx.x * 8 + rt; r < NN; r += gridDim.x * 8) {
        float4 v = buf[(size_t)r * 32 + c4];
        ls[0] += v.x; ls[1] += v.y; ls[2] += v.z; ls[3] += v.w;
        lq[0] += v.x * v.x; lq[1] += v.y * v.y; lq[2] += v.z * v.z; lq[3] += v.w * v.w;
    }
    __shared__ float ss[8][128], sq[8][128];
#pragma unroll
    for (int j = 0; j < 4; j++) { ss[rt][c4 * 4 + j] = ls[j]; sq[rt][c4 * 4 + j] = lq[j]; }
    __syncthreads();
    if (rt == 0) {
#pragma unroll
        for (int j = 0; j < 4; j++) {
            float a = 0.f, b = 0.f;
#pragma unroll
            for (int t = 0; t < 8; t++) { a += ss[t][c4 * 4 + j]; b += sq[t][c4 * 4 + j]; }
            atomicAdd(&st[c4 * 4 + j], a);
            atomicAdd(&st[128 + c4 * 4 + j], b);
        }
    }
}

// ---------------- tensor-core GEMM (M=64 tile, mma.sync bf16, 3-pass compensated) ----------------
// PRE:   apply BN+ReLU (coef from raw statsIn) to A while loading
// OUT16: additionally write fp16 copy of the output (for next gather's neighbor reads)
template <bool PRE, bool OUT16>
__global__ void __launch_bounds__(256, 2) gemm_tc(const float* __restrict__ A,
                                                  const unsigned char* __restrict__ WB,
                                                  const float* __restrict__ bias,
                                                  const float* __restrict__ statsIn,
                                                  const float* __restrict__ bng,
                                                  const float* __restrict__ bnb,
                                                  float* __restrict__ out,
                                                  __half* __restrict__ out16) {
    extern __shared__ unsigned char sm[];
    const uint32_t sbase = smem_u32(sm);
    const int tid = threadIdx.x, wid = tid >> 5, lane = tid & 31;
    const int rowBase = blockIdx.x * 64;

    // ---- B fill via cp.async (69632 B), overlapped with A load/convert ----
    {
        const uint32_t sB = sbase + 2u * ATB;
#pragma unroll
        for (int i = 0; i < 17; i++) {
            uint32_t q = (uint32_t)(tid + i * 256) * 16u;
            cp16(sB + q, WB + q);
        }
        asm volatile("cp.async.commit_group;" ::: "memory");
    }
    // ---- A fill: warp per row (lane = 4 channels), BN optional, bf16 hi/lo split ----
    {
        const int k0 = lane * 4;
        float4 ca, cb;
        if (PRE) bn4(statsIn, bng, bnb, k0, ca, cb);
#pragma unroll 2
        for (int it = 0; it < 8; it++) {
            int r = it * 8 + wid;
            int gr = rowBase + r;
            float4 v = make_float4(0.f, 0.f, 0.f, 0.f);
            if (gr < NN) {
                v = __ldg(reinterpret_cast<const float4*>(&A[(size_t)gr * DD + k0]));
                if (PRE) {
                    v.x = fmaxf(ca.x * v.x + cb.x, 0.f);
                    v.y = fmaxf(ca.y * v.y + cb.y, 0.f);
                    v.z = fmaxf(ca.z * v.z + cb.z, 0.f);
                    v.w = fmaxf(ca.w * v.w + cb.w, 0.f);
                }
            }
            __nv_bfloat16 hx = __float2bfloat16(v.x), hy = __float2bfloat16(v.y);
            __nv_bfloat16 hz = __float2bfloat16(v.z), hw = __float2bfloat16(v.w);
            __nv_bfloat16 lx = __float2bfloat16(v.x - __bfloat162float(hx));
            __nv_bfloat16 ly = __float2bfloat16(v.y - __bfloat162float(hy));
            __nv_bfloat16 lz = __float2bfloat16(v.z - __bfloat162float(hz));
            __nv_bfloat16 lw = __float2bfloat16(v.w - __bfloat162float(hw));
            uint32_t h01 = ((uint32_t)__bfloat16_as_ushort(hy) << 16) | __bfloat16_as_ushort(hx);
            uint32_t h23 = ((uint32_t)__bfloat16_as_ushort(hw) << 16) | __bfloat16_as_ushort(hz);
            uint32_t l01 = ((uint32_t)__bfloat16_as_ushort(ly) << 16) | __bfloat16_as_ushort(lx);
            uint32_t l23 = ((uint32_t)__bfloat16_as_ushort(lw) << 16) | __bfloat16_as_ushort(lz);
            uint32_t off = ((uint32_t)r * ASTR + (uint32_t)k0) * 2;
            *reinterpret_cast<uint2*>(sm + off) = make_uint2(h01, h23);
            *reinterpret_cast<uint2*>(sm + ATB + off) = make_uint2(l01, l23);
        }
    }
    asm volatile("cp.async.wait_group 0;" ::: "memory");
    __syncthreads();

    // ---- MMA: warp grid 2 (M) x 4 (N); each warp 32 rows x 32 cols ----
    const int mbase = (wid & 1) * 32;
    const int nbase = (wid >> 1) * 32;

    const uint32_t aoff = (uint32_t)(lane & 15) * (ASTR * 2) + (uint32_t)(lane >> 4) * 16;
    const uint32_t boff = ((uint32_t)((lane >> 4) * 8 + (lane & 7))) * (ASTR * 2)
                        + (uint32_t)((lane >> 3) & 1) * 16;

    float acc[2][4][4];
#pragma unroll
    for (int mt = 0; mt < 2; mt++)
#pragma unroll
        for (int nt = 0; nt < 4; nt++)
#pragma unroll
            for (int j = 0; j < 4; j++) acc[mt][nt][j] = 0.f;

    const uint32_t aB[3] = { sbase, sbase, sbase + ATB };
    const uint32_t bB[3] = { sbase + 2u * ATB, sbase + 2u * ATB + BTB, sbase + 2u * ATB };

#pragma unroll 1
    for (int pass = 0; pass < 3; pass++) {
        const uint32_t pa = aB[pass] + (uint32_t)mbase * (ASTR * 2) + aoff;
        const uint32_t pb = bB[pass] + (uint32_t)nbase * (ASTR * 2) + boff;
#pragma unroll
        for (int ks = 0; ks < 8; ks++) {
            const uint32_t kb = (uint32_t)ks * 32;
            uint32_t a[2][4];
            ldmx4(a[0], pa + kb);
            ldmx4(a[1], pa + 16u * (ASTR * 2) + kb);
            uint32_t b[2][4];
            ldmx4(b[0], pb + kb);
            ldmx4(b[1], pb + 16u * (ASTR * 2) + kb);
#pragma unroll
            for (int mt = 0; mt < 2; mt++)
#pragma unroll
                for (int nt = 0; nt < 4; nt++)
                    mma16816(acc[mt][nt], a[mt], b[nt >> 1][(nt & 1) * 2], b[nt >> 1][(nt & 1) * 2 + 1]);
        }
    }

    // ---- epilogue: bias + store (fp32, optional fp16 copy) ----
    const int g = lane >> 2, t = lane & 3;
#pragma unroll
    for (int mt = 0; mt < 2; mt++) {
#pragma unroll
        for (int half = 0; half < 2; half++) {
            int r = rowBase + mbase + mt * 16 + g + half * 8;
            if (r < NN) {
#pragma unroll
                for (int nt = 0; nt < 4; nt++) {
                    int c = nbase + nt * 8 + t * 2;
                    float2 bb = *reinterpret_cast<const float2*>(&bias[c]);
                    float2 o;
                    o.x = acc[mt][nt][half * 2 + 0] + bb.x;
                    o.y = acc[mt][nt][half * 2 + 1] + bb.y;
                    *reinterpret_cast<float2*>(&out[(size_t)r * DD + c]) = o;
                    if (OUT16) {
                        __half2 ho = __floats2half2_rn(o.x, o.y);
                        *reinterpret_cast<__half2*>(&out16[(size_t)r * DD + c]) = ho;
                    }
                }
            }
        }
    }
}

// ---------------- launch ----------------
extern "C" void kernel_launch(void* const* d_in, const int* in_sizes, int n_in,
                              void* d_out, int out_size) {
    const float* x     = (const float*)d_in[0];
    const int*   row   = (const int*)d_in[1];
    const int*   col   = (const int*)d_in[2];
    const float* c0_w1 = (const float*)d_in[3];
    const float* c0_b1 = (const float*)d_in[4];
    const float* c0_g  = (const float*)d_in[5];
    const float* c0_be = (const float*)d_in[6];
    const float* c0_w2 = (const float*)d_in[7];
    const float* c0_b2 = (const float*)d_in[8];
    const float* bn0_g = (const float*)d_in[9];
    const float* bn0_be= (const float*)d_in[10];
    const float* c1_w1 = (const float*)d_in[11];
    const float* c1_b1 = (const float*)d_in[12];
    const float* c1_g  = (const float*)d_in[13];
    const float* c1_be = (const float*)d_in[14];
    const float* c1_w2 = (const float*)d_in[15];
    const float* c1_b2 = (const float*)d_in[16];
    float* out = (float*)d_out;

    float *S, *H, *T, *ST;
    __half *X16, *T16;
    unsigned char* WB;
    cudaGetSymbolAddress((void**)&S, g_S);
    cudaGetSymbolAddress((void**)&H, g_H);
    cudaGetSymbolAddress((void**)&T, g_T);
    cudaGetSymbolAddress((void**)&X16, g_X16);
    cudaGetSymbolAddress((void**)&T16, g_T16);
    cudaGetSymbolAddress((void**)&ST, g_stats);
    cudaGetSymbolAddress((void**)&WB, g_WB);

    cudaFuncSetAttribute(gemm_tc<false, false>, cudaFuncAttributeMaxDynamicSharedMemorySize, SMEMSZ);
    cudaFuncSetAttribute(gemm_tc<true, true>, cudaFuncAttributeMaxDynamicSharedMemorySize, SMEMSZ);
    cudaFuncSetAttribute(gemm_tc<true, false>, cudaFuncAttributeMaxDynamicSharedMemorySize, SMEMSZ);

    const int histBlocks = (EE + 255) / 256;
    const int gatherBlocks = (NN * 32 + 255) / 256;
    const int gemmBlocks = (NN + 63) / 64;  // 782

    // prep + CSR build (CSR reused by both convs)
    prep_kernel<<<256, 256>>>(x, c0_w1, c0_w2, c1_w1, c1_w2);
    hist_kernel<<<histBlocks, 256>>>(row);
    scan_kernel<<<1, 1024>>>();
    fill_kernel<<<histBlocks, 256>>>(row, col);

    // ---- conv0 ----
    gather_kernel<false><<<gatherBlocks, 256>>>(x, X16, nullptr, nullptr, nullptr, S);
    gemm_tc<false, false><<<gemmBlocks, 256, SMEMSZ>>>(S, WB + 0 * WBYTES, c0_b1,
                                                       nullptr, nullptr, nullptr, H, nullptr);
    stats_kernel<<<256, 256>>>((const float4*)H, ST);
    gemm_tc<true, true><<<gemmBlocks, 256, SMEMSZ>>>(H, WB + 1 * WBYTES, c0_b2,
                                                     ST, c0_g, c0_be, T, T16);

    // ---- conv1 (inter-layer BN+ReLU fused into gather; neighbors from fp16 T copy) ----
    stats_kernel<<<256, 256>>>((const float4*)T, ST + 256);
    gather_kernel<true><<<gatherBlocks, 256>>>(T, T16, ST + 256, bn0_g, bn0_be, S);
    gemm_tc<false, false><<<gemmBlocks, 256, SMEMSZ>>>(S, WB + 2 * WBYTES, c1_b1,
                                                       nullptr, nullptr, nullptr, H, nullptr);
    stats_kernel<<<256, 256>>>((const float4*)H, ST + 512);
    gemm_tc<true, false><<<gemmBlocks, 256, SMEMSZ>>>(H, WB + 3 * WBYTES, c1_b2,
                                                      ST + 512, c1_g, c1_be, out, nullptr);
}

// round 11
// speedup vs baseline: 1.0695x; 1.0695x over previous
#include <cuda_runtime.h>
#include <cuda_bf16.h>
#include <cstdint>

#define NN 50000
#define EE 800000
#define DD 128

#define ASTR 136                     // padded row stride in bf16 (272B; conflict-free ldmatrix)
#define ATB (64 * ASTR * 2)          // 17408 B : 64-row A image (hi or lo)
#define BTB (128 * ASTR * 2)         // 34816 B : 128-row B image (hi or lo)
#define SMEMSZ (2 * ATB + 2 * BTB)   // 104448 B : sAh | sAl | sBh | sBl  (2 CTAs/SM)
#define WBYTES (2 * BTB)
#define NTILES ((NN + 63) / 64)      // 782
#define GEMMGRID 296                 // 2 CTAs/SM * 148 SMs

// ---------------- scratch (static device globals; no allocation) ----------------
__device__ float g_S[NN * DD];
__device__ float g_H[NN * DD];
__device__ float g_T[NN * DD];
__device__ __align__(16) float g_stats[3 * 256];
__device__ unsigned char g_WB[4][WBYTES];
__device__ int g_deg[NN];
__device__ int g_pos[EE];
__device__ int g_off[NN + 1];
__device__ int g_adj[EE];

// ---------------- helpers ----------------
__device__ __forceinline__ uint32_t smem_u32(const void* p) {
    uint32_t a;
    asm("{ .reg .u64 t; cvta.to.shared.u64 t, %1; cvt.u32.u64 %0, t; }" : "=r"(a) : "l"(p));
    return a;
}

__device__ __forceinline__ void cp16(uint32_t s, const void* g) {
    asm volatile("cp.async.ca.shared.global [%0], [%1], 16;" :: "r"(s), "l"(g));
}

__device__ __forceinline__ void ldmx4(uint32_t* r, uint32_t addr) {
    asm volatile("ldmatrix.sync.aligned.m8n8.x4.shared.b16 {%0,%1,%2,%3}, [%4];"
                 : "=r"(r[0]), "=r"(r[1]), "=r"(r[2]), "=r"(r[3]) : "r"(addr));
}

__device__ __forceinline__ void mma16816(float* d, const uint32_t* a, uint32_t b0, uint32_t b1) {
    asm volatile(
        "mma.sync.aligned.m16n8k16.row.col.f32.bf16.bf16.f32 "
        "{%0,%1,%2,%3}, {%4,%5,%6,%7}, {%8,%9}, {%0,%1,%2,%3};"
        : "+f"(d[0]), "+f"(d[1]), "+f"(d[2]), "+f"(d[3])
        : "r"(a[0]), "r"(a[1]), "r"(a[2]), "r"(a[3]), "r"(b0), "r"(b1));
}

// BN coef for 4 channels [k0..k0+3] from raw stats
__device__ __forceinline__ void bn4(const float* __restrict__ st, const float* __restrict__ g,
                                    const float* __restrict__ be, int k0, float4& a, float4& b) {
    float4 s = __ldg(reinterpret_cast<const float4*>(&st[k0]));
    float4 q = __ldg(reinterpret_cast<const float4*>(&st[128 + k0]));
    float4 gg = __ldg(reinterpret_cast<const float4*>(&g[k0]));
    float4 bb = __ldg(reinterpret_cast<const float4*>(&be[k0]));
    const float inv = 1.f / NN;
    float m;
    m = s.x * inv; a.x = gg.x * rsqrtf(q.x * inv - m * m + 1e-5f); b.x = bb.x - m * a.x;
    m = s.y * inv; a.y = gg.y * rsqrtf(q.y * inv - m * m + 1e-5f); b.y = bb.y - m * a.y;
    m = s.z * inv; a.z = gg.z * rsqrtf(q.z * inv - m * m + 1e-5f); b.z = bb.z - m * a.z;
    m = s.w * inv; a.w = gg.w * rsqrtf(q.w * inv - m * m + 1e-5f); b.w = bb.w - m * a.w;
}

// ---------------- prep: zero stats/deg + split all 4 W into bf16 hi/lo images ----------------
__global__ void prep_kernel(const float* __restrict__ w0, const float* __restrict__ w1,
                            const float* __restrict__ w2, const float* __restrict__ w3) {
    int b = blockIdx.x;  // 0..255
    for (int z = b * 256 + threadIdx.x; z < NN; z += 256 * 256) g_deg[z] = 0;
    if (b == 0) {
        for (int j = threadIdx.x; j < 3 * 256; j += 256) g_stats[j] = 0.f;
    }
    int widx = b >> 6;
    const float* W = (widx == 0) ? w0 : (widx == 1) ? w1 : (widx == 2) ? w2 : w3;
    unsigned char* WB = g_WB[widx];
    int idx = (b & 63) * 256 + threadIdx.x;  // 0..16383
    int k = idx >> 7, c = idx & 127;
    float w = W[idx];
    __nv_bfloat16 h = __float2bfloat16(w);
    __nv_bfloat16 l = __float2bfloat16(w - __bfloat162float(h));
    uint32_t off = ((uint32_t)c * ASTR + (uint32_t)k) * 2;
    *reinterpret_cast<__nv_bfloat16*>(WB + off) = h;
    *reinterpret_cast<__nv_bfloat16*>(WB + BTB + off) = l;
}

// ---------------- CSR build ----------------
__global__ void hist_kernel(const int* __restrict__ row) {
    int e = blockIdx.x * 256 + threadIdx.x;
    if (e < EE) g_pos[e] = atomicAdd(&g_deg[__ldg(&row[e])], 1);
}

__global__ void scan_kernel() {  // single block, 1024 threads
    __shared__ int ps[1024];
    const int t = threadIdx.x;
    const int CH = (NN + 1023) / 1024;  // 49
    const int base = t * CH;
    int s = 0;
#pragma unroll 7
    for (int i = 0; i < CH; i++) {
        int n = base + i;
        if (n < NN) s += g_deg[n];
    }
    ps[t] = s;
    __syncthreads();
    for (int d = 1; d < 1024; d <<= 1) {
        int v = (t >= d) ? ps[t - d] : 0;
        __syncthreads();
        ps[t] += v;
        __syncthreads();
    }
    int run = (t == 0) ? 0 : ps[t - 1];
#pragma unroll 7
    for (int i = 0; i < CH; i++) {
        int n = base + i;
        if (n < NN) {
            g_off[n] = run;
            run += g_deg[n];
        }
    }
    if (t == 1023) g_off[NN] = run;
}

__global__ void fill_kernel(const int* __restrict__ row, const int* __restrict__ col) {
    int e = blockIdx.x * 256 + threadIdx.x;
    if (e >= EE) return;
    int r = __ldg(&row[e]);
    g_adj[__ldg(&g_off[r]) + g_pos[e]] = __ldg(&col[e]);
}

// ---------------- gather: dst[i] = pre(feat[i]) + sum_j pre(feat[adj[j]]) ----------------
template <bool PRE>
__global__ void gather_kernel(const float* __restrict__ feat, const float* __restrict__ stats,
                              const float* __restrict__ bng, const float* __restrict__ bnb,
                              float* __restrict__ dst) {
    int node = (blockIdx.x * blockDim.x + threadIdx.x) >> 5;
    if (node >= NN) return;
    const int lane = threadIdx.x & 31;
    const int k0 = lane * 4;

    float4 ca, cb;
    if (PRE) bn4(stats, bng, bnb, k0, ca, cb);
#define PREV(v)                                      \
    if (PRE) {                                       \
        (v).x = fmaxf(ca.x * (v).x + cb.x, 0.f);     \
        (v).y = fmaxf(ca.y * (v).y + cb.y, 0.f);     \
        (v).z = fmaxf(ca.z * (v).z + cb.z, 0.f);     \
        (v).w = fmaxf(ca.w * (v).w + cb.w, 0.f);     \
    }

    float4 acc = __ldg(reinterpret_cast<const float4*>(&feat[(size_t)node * DD + k0]));
    PREV(acc);

    const int s = __ldg(&g_off[node]);
    const int e = __ldg(&g_off[node + 1]);
    int j = s;
    for (; j + 4 <= e; j += 4) {
        int c0 = __ldg(&g_adj[j + 0]);
        int c1 = __ldg(&g_adj[j + 1]);
        int c2 = __ldg(&g_adj[j + 2]);
        int c3 = __ldg(&g_adj[j + 3]);
        float4 v0 = __ldg(reinterpret_cast<const float4*>(&feat[(size_t)c0 * DD + k0]));
        float4 v1 = __ldg(reinterpret_cast<const float4*>(&feat[(size_t)c1 * DD + k0]));
        float4 v2 = __ldg(reinterpret_cast<const float4*>(&feat[(size_t)c2 * DD + k0]));
        float4 v3 = __ldg(reinterpret_cast<const float4*>(&feat[(size_t)c3 * DD + k0]));
        PREV(v0); PREV(v1); PREV(v2); PREV(v3);
        acc.x += (v0.x + v1.x) + (v2.x + v3.x);
        acc.y += (v0.y + v1.y) + (v2.y + v3.y);
        acc.z += (v0.z + v1.z) + (v2.z + v3.z);
        acc.w += (v0.w + v1.w) + (v2.w + v3.w);
    }
    for (; j < e; j++) {
        int c = __ldg(&g_adj[j]);
        float4 v = __ldg(reinterpret_cast<const float4*>(&feat[(size_t)c * DD + k0]));
        PREV(v);
        acc.x += v.x; acc.y += v.y; acc.z += v.z; acc.w += v.w;
    }
    *reinterpret_cast<float4*>(&dst[(size_t)node * DD + k0]) = acc;
#undef PREV
}

// ---------------- column sum & sumsq over NN rows ----------------
__global__ void stats_kernel(const float4* __restrict__ buf, float* __restrict__ st) {
    int c4 = threadIdx.x & 31, rt = threadIdx.x >> 5;
    float ls[4] = {0.f, 0.f, 0.f, 0.f}, lq[4] = {0.f, 0.f, 0.f, 0.f};
    for (int r = blockIdx.x * 8 + rt; r < NN; r += gridDim.x * 8) {
        float4 v = buf[(size_t)r * 32 + c4];
        ls[0] += v.x; ls[1] += v.y; ls[2] += v.z; ls[3] += v.w;
        lq[0] += v.x * v.x; lq[1] += v.y * v.y; lq[2] += v.z * v.z; lq[3] += v.w * v.w;
    }
    __shared__ float ss[8][128], sq[8][128];
#pragma unroll
    for (int j = 0; j < 4; j++) { ss[rt][c4 * 4 + j] = ls[j]; sq[rt][c4 * 4 + j] = lq[j]; }
    __syncthreads();
    if (rt == 0) {
#pragma unroll
        for (int j = 0; j < 4; j++) {
            float a = 0.f, b = 0.f;
#pragma unroll
            for (int t = 0; t < 8; t++) { a += ss[t][c4 * 4 + j]; b += sq[t][c4 * 4 + j]; }
            atomicAdd(&st[c4 * 4 + j], a);
            atomicAdd(&st[128 + c4 * 4 + j], b);
        }
    }
}

// ---------------- persistent tensor-core GEMM (M=64 tiles, B resident per CTA) ----------------
// PRE: apply BN+ReLU (coef from raw statsIn) to A while loading
template <bool PRE>
__global__ void __launch_bounds__(256, 2) gemm_tc(const float* __restrict__ A,
                                                  const unsigned char* __restrict__ WB,
                                                  const float* __restrict__ bias,
                                                  const float* __restrict__ statsIn,
                                                  const float* __restrict__ bng,
                                                  const float* __restrict__ bnb,
                                                  float* __restrict__ out) {
    extern __shared__ unsigned char sm[];
    const uint32_t sbase = smem_u32(sm);
    const int tid = threadIdx.x, wid = tid >> 5, lane = tid & 31;

    // ---- B fill ONCE via cp.async (69632 B) ----
    {
        const uint32_t sB = sbase + 2u * ATB;
#pragma unroll
        for (int i = 0; i < 17; i++) {
            uint32_t q = (uint32_t)(tid + i * 256) * 16u;
            cp16(sB + q, WB + q);
        }
        asm volatile("cp.async.commit_group;" ::: "memory");
    }

    // per-thread invariants
    const int k0 = lane * 4;
    float4 ca, cb;
    if (PRE) bn4(statsIn, bng, bnb, k0, ca, cb);

    const int mbase = (wid & 1) * 32;
    const int nbase = (wid >> 1) * 32;
    const uint32_t aoff = (uint32_t)(lane & 15) * (ASTR * 2) + (uint32_t)(lane >> 4) * 16;
    const uint32_t boff = ((uint32_t)((lane >> 4) * 8 + (lane & 7))) * (ASTR * 2)
                        + (uint32_t)((lane >> 3) & 1) * 16;
    const uint32_t aB[3] = { sbase, sbase, sbase + ATB };
    const uint32_t bB[3] = { sbase + 2u * ATB, sbase + 2u * ATB + BTB, sbase + 2u * ATB };
    const int g = lane >> 2, t = lane & 3;

    bool firstTile = true;

    for (int tile = blockIdx.x; tile < NTILES; tile += GEMMGRID) {
        const int rowBase = tile * 64;

        // ---- A fill: warp per row (lane = 4 channels), BN optional, bf16 hi/lo split ----
#pragma unroll 2
        for (int it = 0; it < 8; it++) {
            int r = it * 8 + wid;
            int gr = rowBase + r;
            float4 v = make_float4(0.f, 0.f, 0.f, 0.f);
            if (gr < NN) {
                v = __ldg(reinterpret_cast<const float4*>(&A[(size_t)gr * DD + k0]));
                if (PRE) {
                    v.x = fmaxf(ca.x * v.x + cb.x, 0.f);
                    v.y = fmaxf(ca.y * v.y + cb.y, 0.f);
                    v.z = fmaxf(ca.z * v.z + cb.z, 0.f);
                    v.w = fmaxf(ca.w * v.w + cb.w, 0.f);
                }
            }
            __nv_bfloat16 hx = __float2bfloat16(v.x), hy = __float2bfloat16(v.y);
            __nv_bfloat16 hz = __float2bfloat16(v.z), hw = __float2bfloat16(v.w);
            __nv_bfloat16 lx = __float2bfloat16(v.x - __bfloat162float(hx));
            __nv_bfloat16 ly = __float2bfloat16(v.y - __bfloat162float(hy));
            __nv_bfloat16 lz = __float2bfloat16(v.z - __bfloat162float(hz));
            __nv_bfloat16 lw = __float2bfloat16(v.w - __bfloat162float(hw));
            uint32_t h01 = ((uint32_t)__bfloat16_as_ushort(hy) << 16) | __bfloat16_as_ushort(hx);
            uint32_t h23 = ((uint32_t)__bfloat16_as_ushort(hw) << 16) | __bfloat16_as_ushort(hz);
            uint32_t l01 = ((uint32_t)__bfloat16_as_ushort(ly) << 16) | __bfloat16_as_ushort(lx);
            uint32_t l23 = ((uint32_t)__bfloat16_as_ushort(lw) << 16) | __bfloat16_as_ushort(lz);
            uint32_t off = ((uint32_t)r * ASTR + (uint32_t)k0) * 2;
            *reinterpret_cast<uint2*>(sm + off) = make_uint2(h01, h23);
            *reinterpret_cast<uint2*>(sm + ATB + off) = make_uint2(l01, l23);
        }
        if (firstTile) {
            asm volatile("cp.async.wait_group 0;" ::: "memory");
            firstTile = false;
        }
        __syncthreads();

        // ---- MMA: warp grid 2 (M) x 4 (N); each warp 32 rows x 32 cols ----
        float acc[2][4][4];
#pragma unroll
        for (int mt = 0; mt < 2; mt++)
#pragma unroll
            for (int nt = 0; nt < 4; nt++)
#pragma unroll
                for (int j = 0; j < 4; j++) acc[mt][nt][j] = 0.f;

#pragma unroll 1
        for (int pass = 0; pass < 3; pass++) {
            const uint32_t pa = aB[pass] + (uint32_t)mbase * (ASTR * 2) + aoff;
            const uint32_t pb = bB[pass] + (uint32_t)nbase * (ASTR * 2) + boff;
#pragma unroll
            for (int ks = 0; ks < 8; ks++) {
                const uint32_t kb = (uint32_t)ks * 32;
                uint32_t a[2][4];
                ldmx4(a[0], pa + kb);
                ldmx4(a[1], pa + 16u * (ASTR * 2) + kb);
                uint32_t b[2][4];
                ldmx4(b[0], pb + kb);
                ldmx4(b[1], pb + 16u * (ASTR * 2) + kb);
#pragma unroll
                for (int mt = 0; mt < 2; mt++)
#pragma unroll
                    for (int nt = 0; nt < 4; nt++)
                        mma16816(acc[mt][nt], a[mt], b[nt >> 1][(nt & 1) * 2], b[nt >> 1][(nt & 1) * 2 + 1]);
            }
        }

        // ---- epilogue: bias + store ----
#pragma unroll
        for (int mt = 0; mt < 2; mt++) {
#pragma unroll
            for (int half = 0; half < 2; half++) {
                int r = rowBase + mbase + mt * 16 + g + half * 8;
                if (r < NN) {
#pragma unroll
                    for (int nt = 0; nt < 4; nt++) {
                        int c = nbase + nt * 8 + t * 2;
                        float2 bb = *reinterpret_cast<const float2*>(&bias[c]);
                        float2 o;
                        o.x = acc[mt][nt][half * 2 + 0] + bb.x;
                        o.y = acc[mt][nt][half * 2 + 1] + bb.y;
                        *reinterpret_cast<float2*>(&out[(size_t)r * DD + c]) = o;
                    }
                }
            }
        }
        __syncthreads();  // A smem reused next tile
    }
}

// ---------------- launch ----------------
extern "C" void kernel_launch(void* const* d_in, const int* in_sizes, int n_in,
                              void* d_out, int out_size) {
    const float* x     = (const float*)d_in[0];
    const int*   row   = (const int*)d_in[1];
    const int*   col   = (const int*)d_in[2];
    const float* c0_w1 = (const float*)d_in[3];
    const float* c0_b1 = (const float*)d_in[4];
    const float* c0_g  = (const float*)d_in[5];
    const float* c0_be = (const float*)d_in[6];
    const float* c0_w2 = (const float*)d_in[7];
    const float* c0_b2 = (const float*)d_in[8];
    const float* bn0_g = (const float*)d_in[9];
    const float* bn0_be= (const float*)d_in[10];
    const float* c1_w1 = (const float*)d_in[11];
    const float* c1_b1 = (const float*)d_in[12];
    const float* c1_g  = (const float*)d_in[13];
    const float* c1_be = (const float*)d_in[14];
    const float* c1_w2 = (const float*)d_in[15];
    const float* c1_b2 = (const float*)d_in[16];
    float* out = (float*)d_out;

    float *S, *H, *T, *ST;
    unsigned char* WB;
    cudaGetSymbolAddress((void**)&S, g_S);
    cudaGetSymbolAddress((void**)&H, g_H);
    cudaGetSymbolAddress((void**)&T, g_T);
    cudaGetSymbolAddress((void**)&ST, g_stats);
    cudaGetSymbolAddress((void**)&WB, g_WB);

    cudaFuncSetAttribute(gemm_tc<false>, cudaFuncAttributeMaxDynamicSharedMemorySize, SMEMSZ);
    cudaFuncSetAttribute(gemm_tc<true>, cudaFuncAttributeMaxDynamicSharedMemorySize, SMEMSZ);

    const int histBlocks = (EE + 255) / 256;
    const int gatherBlocks = (NN * 32 + 255) / 256;

    // prep + CSR build (CSR reused by both convs)
    prep_kernel<<<256, 256>>>(c0_w1, c0_w2, c1_w1, c1_w2);
    hist_kernel<<<histBlocks, 256>>>(row);
    scan_kernel<<<1, 1024>>>();
    fill_kernel<<<histBlocks, 256>>>(row, col);

    // ---- conv0 ----
    gather_kernel<false><<<gatherBlocks, 256>>>(x, nullptr, nullptr, nullptr, S);
    gemm_tc<false><<<GEMMGRID, 256, SMEMSZ>>>(S, WB + 0 * WBYTES, c0_b1,
                                              nullptr, nullptr, nullptr, H);
    stats_kernel<<<256, 256>>>((const float4*)H, ST);
    gemm_tc<true><<<GEMMGRID, 256, SMEMSZ>>>(H, WB + 1 * WBYTES, c0_b2,
                                             ST, c0_g, c0_be, T);

    // ---- conv1 (inter-layer BN+ReLU fused into gather) ----
    stats_kernel<<<256, 256>>>((const float4*)T, ST + 256);
    gather_kernel<true><<<gatherBlocks, 256>>>(T, ST + 256, bn0_g, bn0_be, S);
    gemm_tc<false><<<GEMMGRID, 256, SMEMSZ>>>(S, WB + 2 * WBYTES, c1_b1,
                                              nullptr, nullptr, nullptr, H);
    stats_kernel<<<256, 256>>>((const float4*)H, ST + 512);
    gemm_tc<true><<<GEMMGRID, 256, SMEMSZ>>>(H, WB + 3 * WBYTES, c1_b2,
                                             ST + 512, c1_g, c1_be, out);
}